// round 1
// baseline (speedup 1.0000x reference)
#include <cuda_runtime.h>
#include <math.h>

#define NN 4096
#define CEXP 144.269504089f   /* (1/TAU) * log2(e) */
#define RWIN 0.3725f          /* sqrt(20 / CEXP): cutoff where exp2 term < 2^-20 */

static __device__ float g_xs[NN + 4];   // preds sorted ascending (+padding)
static __device__ float g_ts[NN + 4];   // target permuted alongside (+padding)
static __device__ float g_y[NN];        // y_sorted

// ---------------------------------------------------------------------------
// Kernel A: sort (preds, target) pairs by preds ascending. 1 block bitonic.
// ---------------------------------------------------------------------------
__global__ void sort_pairs_kernel(const float* __restrict__ preds,
                                  const float* __restrict__ target) {
    __shared__ float k[NN];
    __shared__ float v[NN];
    int tid = threadIdx.x;
    for (int i = tid; i < NN; i += 1024) { k[i] = preds[i]; v[i] = target[i]; }
    __syncthreads();
    for (int size = 2; size <= NN; size <<= 1) {
        for (int stride = size >> 1; stride > 0; stride >>= 1) {
            for (int i = tid; i < NN; i += 1024) {
                int j = i ^ stride;
                if (j > i) {
                    bool up = ((i & size) == 0);
                    float ki = k[i], kj = k[j];
                    if ((ki > kj) == up) {
                        k[i] = kj; k[j] = ki;
                        float tv = v[i]; v[i] = v[j]; v[j] = tv;
                    }
                }
            }
            __syncthreads();
        }
    }
    for (int i = tid; i < NN; i += 1024) { g_xs[i] = k[i]; g_ts[i] = v[i]; }
    if (tid < 4) { g_xs[NN + tid] = 1e30f; g_ts[NN + tid] = 0.0f; }
}

// ---------------------------------------------------------------------------
// Kernel B: y_sorted[i] = softmax_j(-(xs_i - x_j)^2/tau) . t_j
// One warp per row. Window [lo,hi) via binary search; terms outside are < 2^-20.
// ---------------------------------------------------------------------------
__global__ void ysoft_kernel() {
    const unsigned FULL = 0xffffffffu;
    const int lane = threadIdx.x & 31;
    const int warp = threadIdx.x >> 5;
    const int row = blockIdx.x * (blockDim.x >> 5) + warp;
    if (row >= NN) return;
    const float xv = g_xs[row];

    int lo = 0, hi = NN;
    if (lane == 0) {
        float t = xv - RWIN;
        int l = 0, r = NN;
        while (l < r) { int m = (l + r) >> 1; if (g_xs[m] < t) l = m + 1; else r = m; }
        lo = l;
    }
    if (lane == 1) {
        float t = xv + RWIN;
        int l = 0, r = NN;
        while (l < r) { int m = (l + r) >> 1; if (g_xs[m] <= t) l = m + 1; else r = m; }
        hi = l;
    }
    lo = __shfl_sync(FULL, lo, 0);
    hi = __shfl_sync(FULL, hi, 1);

    float se = 0.f, st = 0.f;
    int j0 = (lo & ~3) + lane * 4;
    for (int j = j0; j < hi; j += 128) {
        float4 x4 = *reinterpret_cast<const float4*>(g_xs + j);
        float4 t4 = *reinterpret_cast<const float4*>(g_ts + j);
        float d0 = xv - x4.x, d1 = xv - x4.y, d2 = xv - x4.z, d3 = xv - x4.w;
        float a0 = (d0 * d0) * (-CEXP);
        float a1 = (d1 * d1) * (-CEXP);
        float a2 = (d2 * d2) * (-CEXP);
        float a3 = (d3 * d3) * (-CEXP);
        float e0, e1, e2, e3;
        asm("ex2.approx.f32 %0, %1;" : "=f"(e0) : "f"(a0));
        asm("ex2.approx.f32 %0, %1;" : "=f"(e1) : "f"(a1));
        asm("ex2.approx.f32 %0, %1;" : "=f"(e2) : "f"(a2));
        asm("ex2.approx.f32 %0, %1;" : "=f"(e3) : "f"(a3));
        se += e0 + e1 + e2 + e3;
        st = fmaf(e0, t4.x, st);
        st = fmaf(e1, t4.y, st);
        st = fmaf(e2, t4.z, st);
        st = fmaf(e3, t4.w, st);
    }
    for (int off = 16; off; off >>= 1) {
        se += __shfl_down_sync(FULL, se, off);
        st += __shfl_down_sync(FULL, st, off);
    }
    if (lane == 0) g_y[row] = st / se;
}

// ---------------------------------------------------------------------------
// Kernel C: soft_rank via non-increasing isotonic regression (PAV), then
// diff_sum and final loss. Single block, 1024 threads, dynamic shared.
//   1. s = 100*y, bitonic argsort descending (sort -s ascending w/ index)
//   2. z[k] = s[k] - (N-k). Adjacent violating pairs (z[k] >= z[k-1]) always
//      pool -> parallel pre-pooling via prefix scans (deterministic).
//   3. Single-thread PAV over the ~O(100) pre-blocks.
//   4. Expand block means, scatter r[idx[k]] = s[k]-v, reduce sum|dr|.
// ---------------------------------------------------------------------------
__global__ void rank_kernel(float* out, int out_size) {
    extern __shared__ char smem_raw[];
    float* s      = (float*)smem_raw;             // NN
    int*   idx    = (int*)(s + NN);               // NN
    int*   bid    = (int*)(idx + NN);             // NN
    float* bsum   = (float*)(bid + NN);           // NN
    int*   bcnt   = (int*)(bsum + NN);            // NN
    int*   bstart = (int*)(bcnt + NN);            // NN+1
    int*   fstart = (int*)(bstart + NN + 1);      // NN+1
    float* fmean  = (float*)(fstart + NN + 1);    // NN
    float* r      = (float*)(fmean + NN);         // NN (zc, then r)

    __shared__ int   warpTot[32];
    __shared__ int   warpOff[32];
    __shared__ float warpTotF[32];
    __shared__ float warpOffF[32];
    __shared__ int   s_m;
    __shared__ int   s_nb;
    __shared__ float s_red[32];

    const unsigned FULL = 0xffffffffu;
    int tid = threadIdx.x;
    int lane = tid & 31;
    int warp = tid >> 5;

    // 1) load negated scaled values + index payload
    for (int i = tid; i < NN; i += 1024) { s[i] = -g_y[i] * 100.0f; idx[i] = i; }
    __syncthreads();

    // bitonic ascending on -s  == descending on s
    for (int size = 2; size <= NN; size <<= 1) {
        for (int stride = size >> 1; stride > 0; stride >>= 1) {
            for (int i = tid; i < NN; i += 1024) {
                int j = i ^ stride;
                if (j > i) {
                    bool up = ((i & size) == 0);
                    float ki = s[i], kj = s[j];
                    if ((ki > kj) == up) {
                        s[i] = kj; s[j] = ki;
                        int t = idx[i]; idx[i] = idx[j]; idx[j] = t;
                    }
                }
            }
            __syncthreads();
        }
    }
    for (int i = tid; i < NN; i += 1024) s[i] = -s[i];
    __syncthreads();

    // 2a) boundary indicators: new pre-block at k iff s[k-1]-s[k] > 1
    //     (i.e. z[k] < z[k-1], non-violating). Inclusive prefix-sum -> bid.
    int base = tid * 4;
    int b0 = (base > 0) ? (s[base - 1] - s[base] > 1.0f) : 0;
    int b1 = (s[base + 0] - s[base + 1] > 1.0f);
    int b2 = (s[base + 1] - s[base + 2] > 1.0f);
    int b3 = (s[base + 2] - s[base + 3] > 1.0f);
    int p0 = b0, p1 = p0 + b1, p2 = p1 + b2, p3 = p2 + b3;
    int vsc = p3;
    for (int off = 1; off < 32; off <<= 1) {
        int u = __shfl_up_sync(FULL, vsc, off);
        if (lane >= off) vsc += u;
    }
    if (lane == 31) warpTot[warp] = vsc;
    __syncthreads();
    if (warp == 0) {
        int t2 = warpTot[lane];
        int v2 = t2;
        for (int off = 1; off < 32; off <<= 1) {
            int u = __shfl_up_sync(FULL, v2, off);
            if (lane >= off) v2 += u;
        }
        warpOff[lane] = v2 - t2;
    }
    __syncthreads();
    int excl = warpOff[warp] + (vsc - p3);
    int i0 = excl + p0, i1 = excl + p1, i2 = excl + p2, i3 = excl + p3;
    bid[base + 0] = i0; bid[base + 1] = i1; bid[base + 2] = i2; bid[base + 3] = i3;
    // block starts: element k starts block bid[k] iff indicator set (or k==0)
    if (base == 0) bstart[0] = 0;
    if (b0) bstart[i0] = base + 0;
    if (b1) bstart[i1] = base + 1;
    if (b2) bstart[i2] = base + 2;
    if (b3) bstart[i3] = base + 3;
    if (tid == 1023) { s_m = i3 + 1; bstart[i3 + 1] = NN; }

    // 2b) inclusive prefix sum of z into r (used as zc), z[k] = s[k]-(N-k)
    float z0 = s[base + 0] - (float)(NN - base - 0);
    float z1 = s[base + 1] - (float)(NN - base - 1);
    float z2 = s[base + 2] - (float)(NN - base - 2);
    float z3 = s[base + 3] - (float)(NN - base - 3);
    float q0 = z0, q1 = q0 + z1, q2 = q1 + z2, q3 = q2 + z3;
    float vf = q3;
    for (int off = 1; off < 32; off <<= 1) {
        float u = __shfl_up_sync(FULL, vf, off);
        if (lane >= off) vf += u;
    }
    if (lane == 31) warpTotF[warp] = vf;
    __syncthreads();
    if (warp == 0) {
        float t2 = warpTotF[lane];
        float v2 = t2;
        for (int off = 1; off < 32; off <<= 1) {
            float u = __shfl_up_sync(FULL, v2, off);
            if (lane >= off) v2 += u;
        }
        warpOffF[lane] = v2 - t2;
    }
    __syncthreads();
    float exf = warpOffF[warp] + (vf - q3);
    r[base + 0] = exf + q0;
    r[base + 1] = exf + q1;
    r[base + 2] = exf + q2;
    r[base + 3] = exf + q3;
    __syncthreads();

    // 2c) pre-block sums/counts from prefix sums (deterministic, no atomics)
    int m = s_m;
    for (int b = tid; b < m; b += 1024) {
        int st_ = bstart[b], en = bstart[b + 1];
        float lo_ = (st_ > 0) ? r[st_ - 1] : 0.f;
        bsum[b] = r[en - 1] - lo_;
        bcnt[b] = en - st_;
    }
    __syncthreads();

    // 3) single-thread PAV over m pre-blocks (stack reuses bsum/bcnt/bstart
    //    in place: stack pointer sp is always < current read index b).
    if (tid == 0) {
        int sp = 0;
        float tsum = bsum[0];
        float tcnt = (float)bcnt[0];
        int   tst  = 0;
        for (int b = 1; b < m; b++) {
            float nsum = bsum[b];
            float ncnt = (float)bcnt[b];
            int   nst  = bstart[b];
            bool havetop = true;
            // merge while mean(top) <= mean(new)  (counts > 0)
            while (havetop && tsum * ncnt <= nsum * tcnt) {
                nsum += tsum; ncnt += tcnt; nst = tst;
                if (sp > 0) {
                    sp--;
                    tsum = bsum[sp]; tcnt = (float)bcnt[sp]; tst = bstart[sp];
                } else {
                    havetop = false;
                }
            }
            if (havetop) {
                bsum[sp] = tsum; bcnt[sp] = (int)tcnt; bstart[sp] = tst; sp++;
            }
            tsum = nsum; tcnt = ncnt; tst = nst;
        }
        for (int q = 0; q < sp; q++) {
            fstart[q] = bstart[q];
            fmean[q]  = bsum[q] / (float)bcnt[q];
        }
        fstart[sp] = tst;
        fmean[sp]  = tsum / tcnt;
        fstart[sp + 1] = NN;
        s_nb = sp + 1;
    }
    __syncthreads();

    // 4) expand + scatter r[idx[k]] = s[k] - v(block(k))
    int nb = s_nb;
    for (int k = tid; k < NN; k += 1024) {
        int l = 0, h = nb;
        while (l + 1 < h) {
            int mid = (l + h) >> 1;
            if (fstart[mid] <= k) l = mid; else h = mid;
        }
        float val = s[k] - fmean[l];
        r[idx[k]] = val;
    }
    __syncthreads();

    float acc = 0.f;
    for (int i = tid; i < NN - 1; i += 1024) acc += fabsf(r[i + 1] - r[i]);
    for (int off = 16; off; off >>= 1) acc += __shfl_down_sync(FULL, acc, off);
    if (lane == 0) s_red[warp] = acc;
    __syncthreads();
    if (warp == 0) {
        float a2 = s_red[lane];
        for (int off = 16; off; off >>= 1) a2 += __shfl_down_sync(FULL, a2, off);
        if (lane == 0) {
            float diff = a2;
            float xi = 1.0f - 3.0f * diff / ((float)NN * (float)NN - 1.0f);
            out[0] = -xi;
            if (out_size > 1) out[1] = xi;
        }
    }
}

// ---------------------------------------------------------------------------
extern "C" void kernel_launch(void* const* d_in, const int* in_sizes, int n_in,
                              void* d_out, int out_size) {
    const float* preds  = (const float*)d_in[0];
    const float* target = (const float*)d_in[1];
    float* out = (float*)d_out;

    sort_pairs_kernel<<<1, 1024>>>(preds, target);
    ysoft_kernel<<<NN / 8, 256>>>();

    size_t smem = (size_t)(9 * NN + 2) * sizeof(float);
    cudaFuncSetAttribute(rank_kernel, cudaFuncAttributeMaxDynamicSharedMemorySize,
                         (int)smem);
    rank_kernel<<<1, 1024, smem>>>(out, out_size);
}

// round 2
// speedup vs baseline: 2.5282x; 2.5282x over previous
#include <cuda_runtime.h>
#include <math.h>

#define NN 4096
#define CEXP 144.269504089f   /* (1/TAU) * log2(e) */
#define RWIN 0.3725f          /* sqrt(20 / CEXP): cutoff where exp2 term < 2^-20 */

static __device__ float g_xs[NN + 4];   // preds sorted ascending (+padding)
static __device__ float g_ts[NN + 4];   // target permuted alongside (+padding)
static __device__ float g_y[NN];        // y_sorted
static __device__ float g_ss[NN];       // s = 100*y sorted DESCENDING
static __device__ int   g_sidx[NN];     // original indices of that sort

// ---------------------------------------------------------------------------
// Kernel A: rank-by-count sort of (preds, target) by preds ascending.
// 64 blocks x 256 thr. Warp handles 8 rows; 4 lanes per row scan interleaved
// float4 chunks of a full smem copy (broadcast loads, no conflicts).
// ---------------------------------------------------------------------------
__global__ void rank_scatter_pairs(const float* __restrict__ preds,
                                   const float* __restrict__ target) {
    const unsigned FULL = 0xffffffffu;
    __shared__ float sx[NN];
    for (int i = threadIdx.x; i < NN; i += blockDim.x) sx[i] = preds[i];
    __syncthreads();

    int gw   = (blockIdx.x * blockDim.x + threadIdx.x) >> 5;
    int lane = threadIdx.x & 31;
    int row  = gw * 8 + (lane >> 2);
    int q    = lane & 3;
    float xi = sx[row];
    int cnt = 0;
    #pragma unroll 4
    for (int t = 0; t < NN / 16; t++) {
        int j = t * 16 + q * 4;
        float4 v = *reinterpret_cast<const float4*>(sx + j);
        cnt += (v.x < xi) || (v.x == xi && (j + 0) < row);
        cnt += (v.y < xi) || (v.y == xi && (j + 1) < row);
        cnt += (v.z < xi) || (v.z == xi && (j + 2) < row);
        cnt += (v.w < xi) || (v.w == xi && (j + 3) < row);
    }
    cnt += __shfl_xor_sync(FULL, cnt, 1);
    cnt += __shfl_xor_sync(FULL, cnt, 2);
    if (q == 0) {
        g_xs[cnt] = xi;
        g_ts[cnt] = target[row];
    }
    if (blockIdx.x == 0 && threadIdx.x < 4) {
        g_xs[NN + threadIdx.x] = 1e30f;
        g_ts[NN + threadIdx.x] = 0.0f;
    }
}

// ---------------------------------------------------------------------------
// Kernel B: y_sorted[i] = softmax_j(-(xs_i - x_j)^2/tau) . t_j
// One warp per row. Window [lo,hi) via binary search; terms outside < 2^-20.
// ---------------------------------------------------------------------------
__global__ void ysoft_kernel() {
    const unsigned FULL = 0xffffffffu;
    const int lane = threadIdx.x & 31;
    const int warp = threadIdx.x >> 5;
    const int row = blockIdx.x * (blockDim.x >> 5) + warp;
    if (row >= NN) return;
    const float xv = g_xs[row];

    int lo = 0, hi = NN;
    if (lane == 0) {
        float t = xv - RWIN;
        int l = 0, r = NN;
        while (l < r) { int m = (l + r) >> 1; if (g_xs[m] < t) l = m + 1; else r = m; }
        lo = l;
    }
    if (lane == 1) {
        float t = xv + RWIN;
        int l = 0, r = NN;
        while (l < r) { int m = (l + r) >> 1; if (g_xs[m] <= t) l = m + 1; else r = m; }
        hi = l;
    }
    lo = __shfl_sync(FULL, lo, 0);
    hi = __shfl_sync(FULL, hi, 1);

    float se = 0.f, st = 0.f;
    int j0 = (lo & ~3) + lane * 4;
    for (int j = j0; j < hi; j += 128) {
        float4 x4 = *reinterpret_cast<const float4*>(g_xs + j);
        float4 t4 = *reinterpret_cast<const float4*>(g_ts + j);
        float d0 = xv - x4.x, d1 = xv - x4.y, d2 = xv - x4.z, d3 = xv - x4.w;
        float a0 = (d0 * d0) * (-CEXP);
        float a1 = (d1 * d1) * (-CEXP);
        float a2 = (d2 * d2) * (-CEXP);
        float a3 = (d3 * d3) * (-CEXP);
        float e0, e1, e2, e3;
        asm("ex2.approx.f32 %0, %1;" : "=f"(e0) : "f"(a0));
        asm("ex2.approx.f32 %0, %1;" : "=f"(e1) : "f"(a1));
        asm("ex2.approx.f32 %0, %1;" : "=f"(e2) : "f"(a2));
        asm("ex2.approx.f32 %0, %1;" : "=f"(e3) : "f"(a3));
        se += e0 + e1 + e2 + e3;
        st = fmaf(e0, t4.x, st);
        st = fmaf(e1, t4.y, st);
        st = fmaf(e2, t4.z, st);
        st = fmaf(e3, t4.w, st);
    }
    for (int off = 16; off; off >>= 1) {
        se += __shfl_down_sync(FULL, se, off);
        st += __shfl_down_sync(FULL, st, off);
    }
    if (lane == 0) g_y[row] = st / se;
}

// ---------------------------------------------------------------------------
// Kernel D: rank-by-count DESCENDING argsort of s = 100*y; scatter sorted
// values + original indices. Same structure as kernel A.
// ---------------------------------------------------------------------------
__global__ void rank_scatter_y() {
    const unsigned FULL = 0xffffffffu;
    __shared__ float sy[NN];
    for (int i = threadIdx.x; i < NN; i += blockDim.x) sy[i] = g_y[i];
    __syncthreads();

    int gw   = (blockIdx.x * blockDim.x + threadIdx.x) >> 5;
    int lane = threadIdx.x & 31;
    int row  = gw * 8 + (lane >> 2);
    int q    = lane & 3;
    float yi = sy[row];
    int cnt = 0;
    #pragma unroll 4
    for (int t = 0; t < NN / 16; t++) {
        int j = t * 16 + q * 4;
        float4 v = *reinterpret_cast<const float4*>(sy + j);
        cnt += (v.x > yi) || (v.x == yi && (j + 0) < row);
        cnt += (v.y > yi) || (v.y == yi && (j + 1) < row);
        cnt += (v.z > yi) || (v.z == yi && (j + 2) < row);
        cnt += (v.w > yi) || (v.w == yi && (j + 3) < row);
    }
    cnt += __shfl_xor_sync(FULL, cnt, 1);
    cnt += __shfl_xor_sync(FULL, cnt, 2);
    if (q == 0) {
        g_ss[cnt]   = yi * 100.0f;
        g_sidx[cnt] = row;
    }
}

// ---------------------------------------------------------------------------
// Kernel C: soft_rank via non-increasing isotonic regression (PAV), then
// diff_sum and final loss. Single block, 1024 threads, dynamic shared.
// Sorted input comes from kernel D (no bitonic here anymore).
// ---------------------------------------------------------------------------
__global__ void rank_kernel(float* out, int out_size) {
    extern __shared__ char smem_raw[];
    float* s      = (float*)smem_raw;             // NN  (descending)
    int*   idx    = (int*)(s + NN);               // NN
    float* bsum   = (float*)(idx + NN);           // NN
    int*   bcnt   = (int*)(bsum + NN);            // NN
    int*   bstart = (int*)(bcnt + NN);            // NN+1
    int*   fstart = (int*)(bstart + NN + 1);      // NN+1
    float* fmean  = (float*)(fstart + NN + 1);    // NN
    float* r      = (float*)(fmean + NN);         // NN (zc, then r)

    __shared__ int   warpTot[32];
    __shared__ int   warpOff[32];
    __shared__ float warpTotF[32];
    __shared__ float warpOffF[32];
    __shared__ int   s_m;
    __shared__ int   s_nb;
    __shared__ float s_red[32];

    const unsigned FULL = 0xffffffffu;
    int tid = threadIdx.x;
    int lane = tid & 31;
    int warp = tid >> 5;

    for (int i = tid; i < NN; i += 1024) { s[i] = g_ss[i]; idx[i] = g_sidx[i]; }
    __syncthreads();

    // boundary indicators: new pre-block at k iff s[k-1]-s[k] > 1
    int base = tid * 4;
    int b0 = (base > 0) ? (s[base - 1] - s[base] > 1.0f) : 0;
    int b1 = (s[base + 0] - s[base + 1] > 1.0f);
    int b2 = (s[base + 1] - s[base + 2] > 1.0f);
    int b3 = (s[base + 2] - s[base + 3] > 1.0f);
    int p0 = b0, p1 = p0 + b1, p2 = p1 + b2, p3 = p2 + b3;
    int vsc = p3;
    for (int off = 1; off < 32; off <<= 1) {
        int u = __shfl_up_sync(FULL, vsc, off);
        if (lane >= off) vsc += u;
    }
    if (lane == 31) warpTot[warp] = vsc;
    __syncthreads();
    if (warp == 0) {
        int t2 = warpTot[lane];
        int v2 = t2;
        for (int off = 1; off < 32; off <<= 1) {
            int u = __shfl_up_sync(FULL, v2, off);
            if (lane >= off) v2 += u;
        }
        warpOff[lane] = v2 - t2;
    }
    __syncthreads();
    int excl = warpOff[warp] + (vsc - p3);
    int i0 = excl + p0, i1 = excl + p1, i2 = excl + p2, i3 = excl + p3;
    if (base == 0) bstart[0] = 0;
    if (b0) bstart[i0] = base + 0;
    if (b1) bstart[i1] = base + 1;
    if (b2) bstart[i2] = base + 2;
    if (b3) bstart[i3] = base + 3;
    if (tid == 1023) { s_m = i3 + 1; bstart[i3 + 1] = NN; }

    // inclusive prefix sum of z into r, z[k] = s[k]-(N-k)
    float z0 = s[base + 0] - (float)(NN - base - 0);
    float z1 = s[base + 1] - (float)(NN - base - 1);
    float z2 = s[base + 2] - (float)(NN - base - 2);
    float z3 = s[base + 3] - (float)(NN - base - 3);
    float q0 = z0, q1 = q0 + z1, q2 = q1 + z2, q3 = q2 + z3;
    float vf = q3;
    for (int off = 1; off < 32; off <<= 1) {
        float u = __shfl_up_sync(FULL, vf, off);
        if (lane >= off) vf += u;
    }
    if (lane == 31) warpTotF[warp] = vf;
    __syncthreads();
    if (warp == 0) {
        float t2 = warpTotF[lane];
        float v2 = t2;
        for (int off = 1; off < 32; off <<= 1) {
            float u = __shfl_up_sync(FULL, v2, off);
            if (lane >= off) v2 += u;
        }
        warpOffF[lane] = v2 - t2;
    }
    __syncthreads();
    float exf = warpOffF[warp] + (vf - q3);
    r[base + 0] = exf + q0;
    r[base + 1] = exf + q1;
    r[base + 2] = exf + q2;
    r[base + 3] = exf + q3;
    __syncthreads();

    // pre-block sums/counts from prefix sums
    int m = s_m;
    for (int b = tid; b < m; b += 1024) {
        int st_ = bstart[b], en = bstart[b + 1];
        float lo_ = (st_ > 0) ? r[st_ - 1] : 0.f;
        bsum[b] = r[en - 1] - lo_;
        bcnt[b] = en - st_;
    }
    __syncthreads();

    // single-thread PAV over m pre-blocks
    if (tid == 0) {
        int sp = 0;
        float tsum = bsum[0];
        float tcnt = (float)bcnt[0];
        int   tst  = 0;
        for (int b = 1; b < m; b++) {
            float nsum = bsum[b];
            float ncnt = (float)bcnt[b];
            int   nst  = bstart[b];
            bool havetop = true;
            while (havetop && tsum * ncnt <= nsum * tcnt) {
                nsum += tsum; ncnt += tcnt; nst = tst;
                if (sp > 0) {
                    sp--;
                    tsum = bsum[sp]; tcnt = (float)bcnt[sp]; tst = bstart[sp];
                } else {
                    havetop = false;
                }
            }
            if (havetop) {
                bsum[sp] = tsum; bcnt[sp] = (int)tcnt; bstart[sp] = tst; sp++;
            }
            tsum = nsum; tcnt = ncnt; tst = nst;
        }
        for (int q_ = 0; q_ < sp; q_++) {
            fstart[q_] = bstart[q_];
            fmean[q_]  = bsum[q_] / (float)bcnt[q_];
        }
        fstart[sp] = tst;
        fmean[sp]  = tsum / tcnt;
        fstart[sp + 1] = NN;
        s_nb = sp + 1;
    }
    __syncthreads();

    // expand + scatter r[idx[k]] = s[k] - v(block(k))
    int nb = s_nb;
    for (int k = tid; k < NN; k += 1024) {
        int l = 0, h = nb;
        while (l + 1 < h) {
            int mid = (l + h) >> 1;
            if (fstart[mid] <= k) l = mid; else h = mid;
        }
        float val = s[k] - fmean[l];
        r[idx[k]] = val;
    }
    __syncthreads();

    float acc = 0.f;
    for (int i = tid; i < NN - 1; i += 1024) acc += fabsf(r[i + 1] - r[i]);
    for (int off = 16; off; off >>= 1) acc += __shfl_down_sync(FULL, acc, off);
    if (lane == 0) s_red[warp] = acc;
    __syncthreads();
    if (warp == 0) {
        float a2 = s_red[lane];
        for (int off = 16; off; off >>= 1) a2 += __shfl_down_sync(FULL, a2, off);
        if (lane == 0) {
            float diff = a2;
            float xi = 1.0f - 3.0f * diff / ((float)NN * (float)NN - 1.0f);
            out[0] = -xi;
            if (out_size > 1) out[1] = xi;
        }
    }
}

// ---------------------------------------------------------------------------
extern "C" void kernel_launch(void* const* d_in, const int* in_sizes, int n_in,
                              void* d_out, int out_size) {
    const float* preds  = (const float*)d_in[0];
    const float* target = (const float*)d_in[1];
    float* out = (float*)d_out;

    rank_scatter_pairs<<<64, 256>>>(preds, target);
    ysoft_kernel<<<NN / 8, 256>>>();
    rank_scatter_y<<<64, 256>>>();

    size_t smem = (size_t)(8 * NN + 2) * sizeof(float) + 16;
    cudaFuncSetAttribute(rank_kernel, cudaFuncAttributeMaxDynamicSharedMemorySize,
                         (int)smem);
    rank_kernel<<<1, 1024, smem>>>(out, out_size);
}